// round 1
// baseline (speedup 1.0000x reference)
#include <cuda_runtime.h>

// rho' = (A (x) B (x) C) rho (A (x) B (x) C)^T, where A,B are 16x16 rotations
// active only on the top-left 4x4 block, C is 4x4. flat = r*64 + c*4 + j.
//
// One kernel applies L = A(x)B(x)C to every ROW of its input and writes the
// result TRANSPOSED. Launched twice: rho -> scratch (=Z^T with Z = rho L^T),
// then scratch -> out (= (L Z)^{T T} = L rho L^T).

#define RPB 8           // rows per block
#define ROWLEN 1028     // 1024 + 4 pad floats (bank-conflict-free mixing)

__device__ __align__(16) float g_scratch[1024 * 1024];

__global__ __launch_bounds__(256, 4)
void rbs_xform(const float* __restrict__ in,
               float* __restrict__ out,
               const float* __restrict__ thetas)
{
    __shared__ float s[RPB * ROWLEN];
    __shared__ float sM[3][16];   // 0: A4 (row gates), 1: B4 (col), 2: C4 (ch)

    const int t = threadIdx.x;
    const int row0 = blockIdx.x * RPB;

    // ---- issue global loads early (hide latency behind matrix build) ----
    const float4* in4 = reinterpret_cast<const float4*>(in);
    float4 x[RPB];
#pragma unroll
    for (int rr = 0; rr < RPB; ++rr)
        x[rr] = in4[(size_t)(row0 + rr) * 256 + t];

    // ---- build the three 4x4 Givens products from thetas ----
    if (t < 3) {
        float M[16] = {1,0,0,0, 0,1,0,0, 0,0,1,0, 0,0,0,1};
        const int pi[6] = {0,0,0,1,1,2};
        const int pj[6] = {1,2,3,2,3,3};
#pragma unroll
        for (int g = 0; g < 6; ++g) {
            float th = thetas[t * 6 + g];
            float c = cosf(th), sn = sinf(th);
            int i = pi[g], j = pj[g];
#pragma unroll
            for (int k = 0; k < 4; ++k) {
                float ai = M[i*4 + k], aj = M[j*4 + k];
                M[i*4 + k] =  c * ai + sn * aj;   // M <- G(i,j,th) * M
                M[j*4 + k] = -sn * ai +  c * aj;
            }
        }
#pragma unroll
        for (int k = 0; k < 16; ++k) sM[t][k] = M[k];
    }
    __syncthreads();

    // ---- stage 1: j-mode (C4, full 4x4) fused with store to shared ----
    {
        float c00=sM[2][0],  c01=sM[2][1],  c02=sM[2][2],  c03=sM[2][3];
        float c10=sM[2][4],  c11=sM[2][5],  c12=sM[2][6],  c13=sM[2][7];
        float c20=sM[2][8],  c21=sM[2][9],  c22=sM[2][10], c23=sM[2][11];
        float c30=sM[2][12], c31=sM[2][13], c32=sM[2][14], c33=sM[2][15];
#pragma unroll
        for (int rr = 0; rr < RPB; ++rr) {
            float4 v = x[rr];
            float4 y;
            y.x = c00*v.x + c01*v.y + c02*v.z + c03*v.w;
            y.y = c10*v.x + c11*v.y + c12*v.z + c13*v.w;
            y.z = c20*v.x + c21*v.y + c22*v.z + c23*v.w;
            y.w = c30*v.x + c31*v.y + c32*v.z + c33*v.w;
            *reinterpret_cast<float4*>(&s[rr * ROWLEN + 4 * t]) = y;
        }
    }
    __syncthreads();

    // ---- stage 2: c-mode (B4 on c in 0..3, stride 4) ----
    {
        float b00=sM[1][0],  b01=sM[1][1],  b02=sM[1][2],  b03=sM[1][3];
        float b10=sM[1][4],  b11=sM[1][5],  b12=sM[1][6],  b13=sM[1][7];
        float b20=sM[1][8],  b21=sM[1][9],  b22=sM[1][10], b23=sM[1][11];
        float b30=sM[1][12], b31=sM[1][13], b32=sM[1][14], b33=sM[1][15];
#pragma unroll
        for (int h = 0; h < 2; ++h) {
            int it = t + 256 * h;            // (r outer, rr mid, j inner)
            int r  = it >> 5;
            int rr = (it >> 2) & 7;
            int j  = it & 3;
            float* base = &s[rr * ROWLEN + r * 64 + j];
            float v0 = base[0], v1 = base[4], v2 = base[8], v3 = base[12];
            base[0]  = b00*v0 + b01*v1 + b02*v2 + b03*v3;
            base[4]  = b10*v0 + b11*v1 + b12*v2 + b13*v3;
            base[8]  = b20*v0 + b21*v1 + b22*v2 + b23*v3;
            base[12] = b30*v0 + b31*v1 + b32*v2 + b33*v3;
        }
    }
    __syncthreads();

    // ---- stage 3: r-mode (A4 on r in 0..3, stride 64) ----
    {
        float a00=sM[0][0],  a01=sM[0][1],  a02=sM[0][2],  a03=sM[0][3];
        float a10=sM[0][4],  a11=sM[0][5],  a12=sM[0][6],  a13=sM[0][7];
        float a20=sM[0][8],  a21=sM[0][9],  a22=sM[0][10], a23=sM[0][11];
        float a30=sM[0][12], a31=sM[0][13], a32=sM[0][14], a33=sM[0][15];
#pragma unroll
        for (int h = 0; h < 2; ++h) {
            int it = t + 256 * h;            // (c outer, rr mid, j inner)
            int c  = it >> 5;
            int rr = (it >> 2) & 7;
            int j  = it & 3;
            float* base = &s[rr * ROWLEN + c * 4 + j];
            float v0 = base[0], v1 = base[64], v2 = base[128], v3 = base[192];
            base[0]   = a00*v0 + a01*v1 + a02*v2 + a03*v3;
            base[64]  = a10*v0 + a11*v1 + a12*v2 + a13*v3;
            base[128] = a20*v0 + a21*v1 + a22*v2 + a23*v3;
            base[192] = a30*v0 + a31*v1 + a32*v2 + a33*v3;
        }
    }
    __syncthreads();

    // ---- stage 4: transposed write-out (32B per thread per q: full sectors) ----
#pragma unroll
    for (int k = 0; k < 4; ++k) {
        int q = t + 256 * k;
        float4 a, b;
        a.x = s[0 * ROWLEN + q]; a.y = s[1 * ROWLEN + q];
        a.z = s[2 * ROWLEN + q]; a.w = s[3 * ROWLEN + q];
        b.x = s[4 * ROWLEN + q]; b.y = s[5 * ROWLEN + q];
        b.z = s[6 * ROWLEN + q]; b.w = s[7 * ROWLEN + q];
        float4* o = reinterpret_cast<float4*>(out + (size_t)q * 1024 + row0);
        o[0] = a;
        o[1] = b;
    }
}

extern "C" void kernel_launch(void* const* d_in, const int* in_sizes, int n_in,
                              void* d_out, int out_size)
{
    const float* state  = nullptr;
    const float* thetas = nullptr;
    for (int i = 0; i < n_in; ++i) {
        if (in_sizes[i] == 18 && !thetas)
            thetas = (const float*)d_in[i];
        else if (in_sizes[i] == 1024 * 1024 && !state)
            state = (const float*)d_in[i];
    }

    float* scratch = nullptr;
    cudaGetSymbolAddress((void**)&scratch, g_scratch);

    float* out = (float*)d_out;
    rbs_xform<<<1024 / RPB, 256>>>(state, scratch, thetas);   // Z^T
    rbs_xform<<<1024 / RPB, 256>>>(scratch, out, thetas);     // L rho L^T
}